// round 14
// baseline (speedup 1.0000x reference)
#include <cuda_runtime.h>
#include <cuda_fp16.h>
#include <cstdint>

// ---------------- problem constants ----------------
#define NSAMP   131072
#define INF     8
#define NPCE    495
#define KPAD    512
#define NOUT    256
#define MTILE   64           // CTA rows
#define KC      64           // K per chunk
#define NCHUNK  (KPAD / KC)  // 8
#define NTHREADS 384         // warps 0-7 consumers (MMA), 8-11 producers (gen+load)

// A k-major [64 k][64 m] halves, row stride 144B (9x16B granules)
#define AROWB   144
#define ABUF_BYTES (KC * AROWB)          // 9216
// B n-major [256 n][64 k] halves, row stride 144B
#define BROWB   144
#define BBUF_BYTES (NOUT * BROWB)        // 36864

// smem layout (dynamic)
#define OFF_MI  0                        // 512*4 = 2048
#define OFF_H   2048                     // 40 x 64 floats = 10240 -> 12288
#define OFF_A   12288                    // 2 x 9216  -> 30720
#define OFF_B   30720                    // 2 x 36864 -> 104448
#define SMEM_BYTES 104448

// fp16 weights, zero-padded K, [NOUT][KPAD]
__device__ __half w16g[NOUT * KPAD];

__global__ void convert_w_kernel(const float* __restrict__ wgt) {
    int idx = blockIdx.x * blockDim.x + threadIdx.x;   // 131072 total
    int n = idx >> 9, k = idx & (KPAD - 1);
    w16g[idx] = __float2half(k < NPCE ? wgt[n * NPCE + k] : 0.0f);
}

static __device__ __forceinline__ uint32_t smem_u32(const void* p) {
    uint32_t a;
    asm("{ .reg .u64 t; cvta.to.shared.u64 t, %1; cvt.u32.u64 %0, t; }" : "=r"(a) : "l"(p));
    return a;
}

static __device__ __forceinline__ void cp_async16(uint32_t dst, const void* src) {
    asm volatile("cp.async.cg.shared.global [%0], [%1], 16;" :: "r"(dst), "l"(src));
}
#define CP_COMMIT() asm volatile("cp.async.commit_group;" ::: "memory")
#define CP_WAIT0()  asm volatile("cp.async.wait_group 0;" ::: "memory")

static __device__ __forceinline__ void ldm_x4(uint32_t& r0, uint32_t& r1,
                                              uint32_t& r2, uint32_t& r3, uint32_t addr) {
    asm volatile("ldmatrix.sync.aligned.m8n8.x4.shared.b16 {%0,%1,%2,%3}, [%4];"
                 : "=r"(r0), "=r"(r1), "=r"(r2), "=r"(r3) : "r"(addr));
}
static __device__ __forceinline__ void ldm_x4_trans(uint32_t& r0, uint32_t& r1,
                                                    uint32_t& r2, uint32_t& r3, uint32_t addr) {
    asm volatile("ldmatrix.sync.aligned.m8n8.x4.trans.shared.b16 {%0,%1,%2,%3}, [%4];"
                 : "=r"(r0), "=r"(r1), "=r"(r2), "=r"(r3) : "r"(addr));
}
static __device__ __forceinline__ void mma16816(float& c0, float& c1, float& c2, float& c3,
                                                uint32_t a0, uint32_t a1, uint32_t a2, uint32_t a3,
                                                uint32_t b0, uint32_t b1) {
    asm volatile(
        "mma.sync.aligned.m16n8k16.row.col.f32.f16.f16.f32 "
        "{%0,%1,%2,%3}, {%4,%5,%6,%7}, {%8,%9}, {%0,%1,%2,%3};"
        : "+f"(c0), "+f"(c1), "+f"(c2), "+f"(c3)
        : "r"(a0), "r"(a1), "r"(a2), "r"(a3), "r"(b0), "r"(b1));
}

extern __shared__ char smem[];

__global__ void __launch_bounds__(NTHREADS, 1)
pce_fused_kernel(const float* __restrict__ x, const int* __restrict__ mi,
                 float* __restrict__ out)
{
    const int tid  = threadIdx.x;
    const int wid  = tid >> 5;
    const int lane = tid & 31;
    const int m0   = blockIdx.x * MTILE;

    const uint32_t sbase = smem_u32(smem);
    unsigned* mi_s = (unsigned*)(smem + OFF_MI);
    float*    ht   = (float*)(smem + OFF_H);     // HT[off][m], stride 64 floats

    // ---- all threads: pack multi-indices (8-bit slots, offset = dim*5+order) ----
    for (int t = tid; t < KPAD; t += NTHREADS) {
        unsigned packed = 0;
        if (t < NPCE) {
            int slot = 0;
            #pragma unroll
            for (int j = 0; j < INF; j++) {
                int o = mi[t * INF + j];
                if (o > 0) { packed |= (unsigned)(j * 5 + o) << (8 * slot); slot++; }
            }
        }
        mi_s[t] = packed;
    }

    // ---- Hermite table, transposed HT[j][m] for this CTA's 64 samples ----
    if (tid < MTILE) {
        const float4* xr = (const float4*)(x + (size_t)(m0 + tid) * INF);
        float4 xa = xr[0], xb = xr[1];
        float vx[8] = {xa.x, xa.y, xa.z, xa.w, xb.x, xb.y, xb.z, xb.w};
        #pragma unroll
        for (int j = 0; j < INF; j++) {
            float v  = vx[j];
            float h2 = v * v - 1.f;
            float h3 = v * h2 - 2.f * v;
            float h4 = v * h3 - 3.f * h2;
            ht[(j * 5 + 0) * MTILE + tid] = 1.f;
            ht[(j * 5 + 1) * MTILE + tid] = v;
            ht[(j * 5 + 2) * MTILE + tid] = h2 * 0.70710678118654752f;
            ht[(j * 5 + 3) * MTILE + tid] = h3 * 0.40824829046386302f;
            ht[(j * 5 + 4) * MTILE + tid] = h4 * 0.20412414523193151f;
        }
    }
    __syncthreads();

    const bool producer = (wid >= 8);
    const int  ptid = tid - 256;        // 0..127 for producers

    // producer: generate A chunk (64 k x 64 m halves) + load B chunk
    auto produce = [&](int c, int buf) {
        const int k0 = c * KC;
        const float4* ht4 = (const float4*)ht;     // [off][mq], 16 float4/row
        const uint32_t adst = sbase + OFF_A + buf * ABUF_BYTES;
        #pragma unroll
        for (int i = 0; i < 8; i++) {
            int idx = ptid + i * 128;              // 0..1023 quads
            int k = idx >> 4, mq = idx & 15;
            unsigned p = mi_s[k0 + k];
            float4 a = ht4[(p & 255) * 16 + mq];   // p==0 -> HT row 0 = ones
            p >>= 8;
            while (p) {                            // warp-uniform slot skip
                float4 b = ht4[(p & 255) * 16 + mq];
                a.x *= b.x; a.y *= b.y; a.z *= b.z; a.w *= b.w;
                p >>= 8;
            }
            __half2 h01 = __floats2half2_rn(a.x, a.y);
            __half2 h23 = __floats2half2_rn(a.z, a.w);
            uint2 v = make_uint2(*(uint32_t*)&h01, *(uint32_t*)&h23);
            *(uint2*)(smem + OFF_A + buf * ABUF_BYTES + k * AROWB + mq * 8) = v;
            (void)adst;
        }
        // B: 256 n-rows x 128B; 2048 granules / 128 producer threads
        const uint32_t bdst = sbase + OFF_B + buf * BBUF_BYTES;
        #pragma unroll
        for (int j = 0; j < 16; j++) {
            int idx = ptid + j * 128;              // 0..2047
            int n = idx >> 3, g = idx & 7;
            cp_async16(bdst + n * BROWB + g * 16,
                       w16g + (size_t)n * KPAD + c * KC + g * 8);
        }
        CP_COMMIT();
        CP_WAIT0();
    };

    // consumers: 2(m) x 4(n) warps, each 32m x 64n (R13-validated mainloop)
    const int warp_m = wid >> 2;   // 0..1 (consumers only)
    const int warp_n = wid & 3;    // 0..3

    float acc[2][8][4];
    #pragma unroll
    for (int a = 0; a < 2; a++)
        #pragma unroll
        for (int b = 0; b < 8; b++)
            #pragma unroll
            for (int r = 0; r < 4; r++) acc[a][b][r] = 0.f;

    if (producer) produce(0, 0);
    __syncthreads();               // stage 0 ready

    const int a_row_off = (lane & 7) + ((lane >> 4) & 1) * 8;
    const int a_m_off   = ((lane >> 3) & 1) * 8;

    for (int c = 0; c < NCHUNK; c++) {
        const int cb = c & 1;

        if (producer) {
            if (c + 1 < NCHUNK) produce(c + 1, cb ^ 1);
        } else {
            const uint32_t abase = sbase + OFF_A + cb * ABUF_BYTES;
            const uint32_t b_base = sbase + OFF_B + cb * BBUF_BYTES
                                  + (warp_n * 64 + ((lane >> 4) * 8) + (lane & 7)) * BROWB
                                  + ((lane >> 3) & 1) * 16;
            #pragma unroll
            for (int kb = 0; kb < 4; kb++) {
                uint32_t af[2][4], bf[4][4];
                #pragma unroll
                for (int mb = 0; mb < 2; mb++)
                    ldm_x4_trans(af[mb][0], af[mb][1], af[mb][2], af[mb][3],
                                 abase + (kb * 16 + a_row_off) * AROWB
                                       + (warp_m * 32 + mb * 16 + a_m_off) * 2);
                #pragma unroll
                for (int np = 0; np < 4; np++)
                    ldm_x4(bf[np][0], bf[np][1], bf[np][2], bf[np][3],
                           b_base + np * 16 * BROWB + kb * 32);
                #pragma unroll
                for (int mb = 0; mb < 2; mb++)
                    #pragma unroll
                    for (int nb = 0; nb < 8; nb++)
                        mma16816(acc[mb][nb][0], acc[mb][nb][1], acc[mb][nb][2], acc[mb][nb][3],
                                 af[mb][0], af[mb][1], af[mb][2], af[mb][3],
                                 bf[nb >> 1][(nb & 1) * 2], bf[nb >> 1][(nb & 1) * 2 + 1]);
            }
        }
        __syncthreads();           // stage c consumed / stage c+1 published
    }

    // ---- epilogue: consumers store fp32 results ----
    if (!producer) {
        const int mw = m0 + warp_m * 32;
        const int nw = warp_n * 64;
        const int rq = lane >> 2;
        const int cq = 2 * (lane & 3);
        #pragma unroll
        for (int mb = 0; mb < 2; mb++) {
            #pragma unroll
            for (int nb = 0; nb < 8; nb++) {
                const int row = mw + mb * 16 + rq;
                const int col = nw + nb * 8 + cq;
                *(float2*)(out + (size_t)row * NOUT + col)
                    = make_float2(acc[mb][nb][0], acc[mb][nb][1]);
                *(float2*)(out + (size_t)(row + 8) * NOUT + col)
                    = make_float2(acc[mb][nb][2], acc[mb][nb][3]);
            }
        }
    }
}

extern "C" void kernel_launch(void* const* d_in, const int* in_sizes, int n_in,
                              void* d_out, int out_size) {
    const float* x   = (const float*)d_in[0];
    const float* wgt = (const float*)d_in[1];
    const int*   mi  = (const int*)d_in[2];
    float* out = (float*)d_out;

    convert_w_kernel<<<(NOUT * KPAD) / 256, 256>>>(wgt);

    cudaFuncSetAttribute(pce_fused_kernel,
                         cudaFuncAttributeMaxDynamicSharedMemorySize, SMEM_BYTES);
    pce_fused_kernel<<<NSAMP / MTILE, NTHREADS, SMEM_BYTES>>>(x, mi, out);
}

// round 15
// speedup vs baseline: 1.2160x; 1.2160x over previous
#include <cuda_runtime.h>
#include <cuda_fp16.h>
#include <cstdint>

// ---------------- problem constants ----------------
#define NSAMP   131072
#define INF     8
#define NPCE    495
#define KPAD    512
#define NOUT    256
#define PTILE   128          // psi tile rows
#define MTILE   64           // GEMM CTA rows
#define KC      64           // K per chunk
#define NCHUNK  (KPAD / KC)  // 8
#define NSTAGE  2
#define NSEG    8            // pipeline segments
#define SEG_SAMPLES (NSAMP / NSEG)       // 16384

// A k-major [64 k][64 m] halves, row stride 144B (9x16B granules)
#define AROWB   144
#define ABUF_BYTES (KC * AROWB)          // 9216
// B n-major [256 n][64 k] halves, row stride 144B
#define BROWB   144
#define BBUF_BYTES (NOUT * BROWB)        // 36864
#define OFF_A   0
#define OFF_B   (NSTAGE * ABUF_BYTES)    // 18432
#define GEMM_SMEM (OFF_B + NSTAGE * BBUF_BYTES)   // 92160 (x2 CTAs = 184K)

// fp16 weights, zero-padded K, [NOUT][KPAD]
__device__ __half w16g[NOUT * KPAD];
// psi staged fp16, [k][m] layout (k-major rows of 131072 halves)
__device__ __align__(16) __half psi16[(size_t)KPAD * NSAMP];

static __device__ __forceinline__ uint32_t smem_u32(const void* p) {
    uint32_t a;
    asm("{ .reg .u64 t; cvta.to.shared.u64 t, %1; cvt.u32.u64 %0, t; }" : "=r"(a) : "l"(p));
    return a;
}

// ---------------- W convert ----------------
__global__ void __launch_bounds__(256)
convert_w_kernel(const float* __restrict__ wgt) {
    int idx = blockIdx.x * 256 + threadIdx.x;    // 131072 total
    int n = idx >> 9, k = idx & (KPAD - 1);
    w16g[idx] = __float2half(k < NPCE ? wgt[n * NPCE + k] : 0.0f);
}

// ---------------- psi generation (R13-validated), segment-based ----------------
__global__ void __launch_bounds__(256)
psi_gen_kernel(const float* __restrict__ x, const int* __restrict__ mi, int tile_base)
{
    __shared__ unsigned mi_s[KPAD];
    __shared__ float    ht[40 * PTILE];     // HT[off][m]
    const int tid = threadIdx.x;
    const int m0  = (tile_base + blockIdx.x) * PTILE;

    for (int t = tid; t < KPAD; t += 256) {
        unsigned packed = 0;
        if (t < NPCE) {
            int slot = 0;
            #pragma unroll
            for (int j = 0; j < INF; j++) {
                int o = mi[t * INF + j];
                if (o > 0) { packed |= (unsigned)(j * 5 + o) << (8 * slot); slot++; }
            }
        }
        mi_s[t] = packed;
    }

    if (tid < PTILE) {
        const float4* xr = (const float4*)(x + (size_t)(m0 + tid) * INF);
        float4 xa = xr[0], xb = xr[1];
        float vx[8] = {xa.x, xa.y, xa.z, xa.w, xb.x, xb.y, xb.z, xb.w};
        #pragma unroll
        for (int j = 0; j < INF; j++) {
            float v  = vx[j];
            float h2 = v * v - 1.f;
            float h3 = v * h2 - 2.f * v;
            float h4 = v * h3 - 3.f * h2;
            ht[(j * 5 + 0) * PTILE + tid] = 1.f;
            ht[(j * 5 + 1) * PTILE + tid] = v;
            ht[(j * 5 + 2) * PTILE + tid] = h2 * 0.70710678118654752f;
            ht[(j * 5 + 3) * PTILE + tid] = h3 * 0.40824829046386302f;
            ht[(j * 5 + 4) * PTILE + tid] = h4 * 0.20412414523193151f;
        }
    }
    __syncthreads();

    const float4* ht4 = (const float4*)ht;    // [off][mq], 32 float4 per row
    #pragma unroll 4
    for (int it = 0; it < 64; it++) {
        int idx = it * 256 + tid;             // 0..16383
        int k = idx >> 5, mq = idx & 31;
        unsigned p = mi_s[k];
        float4 a = ht4[(p & 255) * 32 + mq];  // p==0 -> HT row 0 = ones
        p >>= 8;
        while (p) {                           // warp-uniform slot-count skip
            float4 b = ht4[(p & 255) * 32 + mq];
            a.x *= b.x; a.y *= b.y; a.z *= b.z; a.w *= b.w;
            p >>= 8;
        }
        __half2 h01 = __floats2half2_rn(a.x, a.y);
        __half2 h23 = __floats2half2_rn(a.z, a.w);
        uint2 v = make_uint2(*(uint32_t*)&h01, *(uint32_t*)&h23);
        *(uint2*)(psi16 + (size_t)k * NSAMP + m0 + 4 * mq) = v;
    }
}

// ================= GEMM (R13-validated), segment-based =======================
static __device__ __forceinline__ void cp_async16(uint32_t dst, const void* src) {
    asm volatile("cp.async.cg.shared.global [%0], [%1], 16;" :: "r"(dst), "l"(src));
}
#define CP_COMMIT() asm volatile("cp.async.commit_group;" ::: "memory")
#define CP_WAIT0()  asm volatile("cp.async.wait_group 0;" ::: "memory")

static __device__ __forceinline__ void ldm_x4(uint32_t& r0, uint32_t& r1,
                                              uint32_t& r2, uint32_t& r3, uint32_t addr) {
    asm volatile("ldmatrix.sync.aligned.m8n8.x4.shared.b16 {%0,%1,%2,%3}, [%4];"
                 : "=r"(r0), "=r"(r1), "=r"(r2), "=r"(r3) : "r"(addr));
}
static __device__ __forceinline__ void ldm_x4_trans(uint32_t& r0, uint32_t& r1,
                                                    uint32_t& r2, uint32_t& r3, uint32_t addr) {
    asm volatile("ldmatrix.sync.aligned.m8n8.x4.trans.shared.b16 {%0,%1,%2,%3}, [%4];"
                 : "=r"(r0), "=r"(r1), "=r"(r2), "=r"(r3) : "r"(addr));
}
static __device__ __forceinline__ void mma16816(float& c0, float& c1, float& c2, float& c3,
                                                uint32_t a0, uint32_t a1, uint32_t a2, uint32_t a3,
                                                uint32_t b0, uint32_t b1) {
    asm volatile(
        "mma.sync.aligned.m16n8k16.row.col.f32.f16.f16.f32 "
        "{%0,%1,%2,%3}, {%4,%5,%6,%7}, {%8,%9}, {%0,%1,%2,%3};"
        : "+f"(c0), "+f"(c1), "+f"(c2), "+f"(c3)
        : "r"(a0), "r"(a1), "r"(a2), "r"(a3), "r"(b0), "r"(b1));
}

extern __shared__ char smem[];

__global__ void __launch_bounds__(256, 2)
pce_gemm_kernel(float* __restrict__ out, int m_base)
{
    const int tid  = threadIdx.x;
    const int wid  = tid >> 5;
    const int lane = tid & 31;
    const int m0   = m_base + blockIdx.x * MTILE;

    const uint32_t sbase = smem_u32(smem);

    auto load_stage = [&](int c, int buf) {
        // A: 64 k-rows x 128B from psi16[k][m0..m0+64); 512 granules / 256 thr
        const uint32_t adst = sbase + OFF_A + buf * ABUF_BYTES;
        #pragma unroll
        for (int j = 0; j < 2; j++) {
            int idx = tid + j * 256;             // 0..511
            int row = idx >> 3, g = idx & 7;
            cp_async16(adst + row * AROWB + g * 16,
                       psi16 + (size_t)(c * KC + row) * NSAMP + m0 + g * 8);
        }
        // B: 256 n-rows x 128B from w16g; 2048 granules / 256 thr
        const uint32_t bdst = sbase + OFF_B + buf * BBUF_BYTES;
        #pragma unroll
        for (int j = 0; j < 8; j++) {
            int idx = tid + j * 256;             // 0..2047
            int n = idx >> 3, g = idx & 7;
            cp_async16(bdst + n * BROWB + g * 16,
                       w16g + (size_t)n * KPAD + c * KC + g * 8);
        }
        CP_COMMIT();
    };

    // warp tiling: 2(m) x 4(n), each 32m x 64n
    const int warp_m = wid >> 2;   // 0..1
    const int warp_n = wid & 3;    // 0..3

    float acc[2][8][4];
    #pragma unroll
    for (int a = 0; a < 2; a++)
        #pragma unroll
        for (int b = 0; b < 8; b++)
            #pragma unroll
            for (int r = 0; r < 4; r++) acc[a][b][r] = 0.f;

    load_stage(0, 0);

    const int a_row_off = (lane & 7) + ((lane >> 4) & 1) * 8;
    const int a_m_off   = ((lane >> 3) & 1) * 8;

    for (int c = 0; c < NCHUNK; c++) {
        const int cb = c & 1;
        CP_WAIT0();
        __syncthreads();

        if (c + 1 < NCHUNK)
            load_stage(c + 1, cb ^ 1);

        const uint32_t abase = sbase + OFF_A + cb * ABUF_BYTES;
        const uint32_t b_base = sbase + OFF_B + cb * BBUF_BYTES
                              + (warp_n * 64 + ((lane >> 4) * 8) + (lane & 7)) * BROWB
                              + ((lane >> 3) & 1) * 16;

        #pragma unroll
        for (int kb = 0; kb < 4; kb++) {
            uint32_t af[2][4], bf[4][4];
            #pragma unroll
            for (int mb = 0; mb < 2; mb++)
                ldm_x4_trans(af[mb][0], af[mb][1], af[mb][2], af[mb][3],
                             abase + (kb * 16 + a_row_off) * AROWB
                                   + (warp_m * 32 + mb * 16 + a_m_off) * 2);
            #pragma unroll
            for (int np = 0; np < 4; np++)
                ldm_x4(bf[np][0], bf[np][1], bf[np][2], bf[np][3],
                       b_base + np * 16 * BROWB + kb * 32);
            #pragma unroll
            for (int mb = 0; mb < 2; mb++)
                #pragma unroll
                for (int nb = 0; nb < 8; nb++)
                    mma16816(acc[mb][nb][0], acc[mb][nb][1], acc[mb][nb][2], acc[mb][nb][3],
                             af[mb][0], af[mb][1], af[mb][2], af[mb][3],
                             bf[nb >> 1][(nb & 1) * 2], bf[nb >> 1][(nb & 1) * 2 + 1]);
        }
    }

    // epilogue: direct fp32 stores
    {
        const int mw = m0 + warp_m * 32;
        const int nw = warp_n * 64;
        const int rq = lane >> 2;
        const int cq = 2 * (lane & 3);
        #pragma unroll
        for (int mb = 0; mb < 2; mb++) {
            #pragma unroll
            for (int nb = 0; nb < 8; nb++) {
                const int row = mw + mb * 16 + rq;
                const int col = nw + nb * 8 + cq;
                *(float2*)(out + (size_t)row * NOUT + col)
                    = make_float2(acc[mb][nb][0], acc[mb][nb][1]);
                *(float2*)(out + (size_t)(row + 8) * NOUT + col)
                    = make_float2(acc[mb][nb][2], acc[mb][nb][3]);
            }
        }
    }
}

extern "C" void kernel_launch(void* const* d_in, const int* in_sizes, int n_in,
                              void* d_out, int out_size) {
    const float* x   = (const float*)d_in[0];
    const float* wgt = (const float*)d_in[1];
    const int*   mi  = (const int*)d_in[2];
    float* out = (float*)d_out;

    cudaFuncSetAttribute(pce_gemm_kernel,
                         cudaFuncAttributeMaxDynamicSharedMemorySize, GEMM_SMEM);

    // Fork-join pipeline inside graph capture: psi segments on side stream,
    // GEMM segments on main stream gated per-segment by events.
    cudaStream_t s2;
    cudaStreamCreateWithFlags(&s2, cudaStreamNonBlocking);
    cudaEvent_t fork, seg_done[NSEG];
    cudaEventCreateWithFlags(&fork, cudaEventDisableTiming);
    for (int i = 0; i < NSEG; i++)
        cudaEventCreateWithFlags(&seg_done[i], cudaEventDisableTiming);

    convert_w_kernel<<<(NOUT * KPAD) / 256, 256>>>(wgt);

    cudaEventRecord(fork, 0);
    cudaStreamWaitEvent(s2, fork, 0);

    const int tiles_per_seg = SEG_SAMPLES / PTILE;   // 128
    for (int i = 0; i < NSEG; i++) {
        psi_gen_kernel<<<tiles_per_seg, 256, 0, s2>>>(x, mi, i * tiles_per_seg);
        cudaEventRecord(seg_done[i], s2);
    }

    const int ctas_per_seg = SEG_SAMPLES / MTILE;    // 256
    for (int i = 0; i < NSEG; i++) {
        cudaStreamWaitEvent(0, seg_done[i], 0);
        pce_gemm_kernel<<<ctas_per_seg, 256, GEMM_SMEM>>>(out, i * SEG_SAMPLES);
    }
}

// round 16
// speedup vs baseline: 1.3238x; 1.0887x over previous
#include <cuda_runtime.h>
#include <cuda_fp16.h>
#include <cstdint>

// ---------------- problem constants ----------------
#define NSAMP   131072
#define INF     8
#define NPCE    495
#define KPAD    512
#define NOUT    256
#define PTILE   128          // psi tile rows (samples per psi block)
#define KSPLIT  4            // psi blocks per tile along k (128 k-rows each)
#define MTILE   64           // GEMM CTA rows (R13-validated)
#define KC      64           // K per chunk
#define NCHUNK  (KPAD / KC)  // 8
#define NSTAGE  2

// A k-major [64 k][64 m] halves, row stride 144B (9x16B granules)
#define AROWB   144
#define ABUF_BYTES (KC * AROWB)          // 9216
// B n-major [256 n][64 k] halves, row stride 144B
#define BROWB   144
#define BBUF_BYTES (NOUT * BROWB)        // 36864
#define OFF_A   0
#define OFF_B   (NSTAGE * ABUF_BYTES)    // 18432
#define GEMM_SMEM (OFF_B + NSTAGE * BBUF_BYTES)   // 92160 (x2 CTAs = 184K)

// fp16 weights, zero-padded K, [NOUT][KPAD]
__device__ __half w16g[NOUT * KPAD];
// psi staged fp16, [k][m] layout (k-major rows of 131072 halves)
__device__ __align__(16) __half psi16[(size_t)KPAD * NSAMP];

static __device__ __forceinline__ uint32_t smem_u32(const void* p) {
    uint32_t a;
    asm("{ .reg .u64 t; cvta.to.shared.u64 t, %1; cvt.u32.u64 %0, t; }" : "=r"(a) : "l"(p));
    return a;
}

// ===== fused pre-kernel: blocks 0-511 convert W; blocks 512+ psi (k-split) ===
__global__ void __launch_bounds__(256)
pce_pre_kernel(const float* __restrict__ x, const float* __restrict__ wgt,
               const int* __restrict__ mi)
{
    const int tid = threadIdx.x;

    if (blockIdx.x < 512) {
        int idx = blockIdx.x * 256 + tid;        // 0..131071
        int n = idx >> 9, k = idx & (KPAD - 1);
        w16g[idx] = __float2half(k < NPCE ? wgt[n * NPCE + k] : 0.0f);
        return;
    }

    // ---- psi: block = 128 samples x 128 k-rows ----
    __shared__ unsigned mi_s[128];
    __shared__ float    ht[40 * PTILE];     // HT[off][m]
    const int pb   = blockIdx.x - 512;
    const int m0   = (pb >> 2) * PTILE;     // tile
    const int k0   = (pb & (KSPLIT - 1)) * 128;

    if (tid < 128) {
        int t = k0 + tid;
        unsigned packed = 0;
        if (t < NPCE) {
            int slot = 0;
            #pragma unroll
            for (int j = 0; j < INF; j++) {
                int o = mi[t * INF + j];
                if (o > 0) { packed |= (unsigned)(j * 5 + o) << (8 * slot); slot++; }
            }
        }
        mi_s[tid] = packed;
    }

    if (tid < PTILE) {
        const float4* xr = (const float4*)(x + (size_t)(m0 + tid) * INF);
        float4 xa = xr[0], xb = xr[1];
        float vx[8] = {xa.x, xa.y, xa.z, xa.w, xb.x, xb.y, xb.z, xb.w};
        #pragma unroll
        for (int j = 0; j < INF; j++) {
            float v  = vx[j];
            float h2 = v * v - 1.f;
            float h3 = v * h2 - 2.f * v;
            float h4 = v * h3 - 3.f * h2;
            ht[(j * 5 + 0) * PTILE + tid] = 1.f;
            ht[(j * 5 + 1) * PTILE + tid] = v;
            ht[(j * 5 + 2) * PTILE + tid] = h2 * 0.70710678118654752f;
            ht[(j * 5 + 3) * PTILE + tid] = h3 * 0.40824829046386302f;
            ht[(j * 5 + 4) * PTILE + tid] = h4 * 0.20412414523193151f;
        }
    }
    __syncthreads();

    // 128 k-rows x 16 m-groups (8 m each); 2048 items / 256 thr = 8 iters.
    // Two independent float4 product chains per item; 16B psi stores.
    const float4* ht4 = (const float4*)ht;   // [off][mq], 32 float4 per row
    #pragma unroll
    for (int it = 0; it < 8; it++) {
        int idx = it * 256 + tid;            // 0..2047
        int k = idx >> 4, mg = idx & 15;
        unsigned p = mi_s[k];
        float4 a0 = ht4[(p & 255) * 32 + 2 * mg];
        float4 a1 = ht4[(p & 255) * 32 + 2 * mg + 1];
        p >>= 8;
        while (p) {                          // slot-count skip (<=3 more)
            const float4 b0 = ht4[(p & 255) * 32 + 2 * mg];
            const float4 b1 = ht4[(p & 255) * 32 + 2 * mg + 1];
            a0.x *= b0.x; a0.y *= b0.y; a0.z *= b0.z; a0.w *= b0.w;
            a1.x *= b1.x; a1.y *= b1.y; a1.z *= b1.z; a1.w *= b1.w;
            p >>= 8;
        }
        __half2 h0 = __floats2half2_rn(a0.x, a0.y);
        __half2 h1 = __floats2half2_rn(a0.z, a0.w);
        __half2 h2 = __floats2half2_rn(a1.x, a1.y);
        __half2 h3 = __floats2half2_rn(a1.z, a1.w);
        uint4 v = make_uint4(*(uint32_t*)&h0, *(uint32_t*)&h1,
                             *(uint32_t*)&h2, *(uint32_t*)&h3);
        *(uint4*)(psi16 + (size_t)(k0 + k) * NSAMP + m0 + 8 * mg) = v;
    }
}

// ================= GEMM (byte-identical to R13) ==============================
static __device__ __forceinline__ void cp_async16(uint32_t dst, const void* src) {
    asm volatile("cp.async.cg.shared.global [%0], [%1], 16;" :: "r"(dst), "l"(src));
}
#define CP_COMMIT() asm volatile("cp.async.commit_group;" ::: "memory")
#define CP_WAIT0()  asm volatile("cp.async.wait_group 0;" ::: "memory")

static __device__ __forceinline__ void ldm_x4(uint32_t& r0, uint32_t& r1,
                                              uint32_t& r2, uint32_t& r3, uint32_t addr) {
    asm volatile("ldmatrix.sync.aligned.m8n8.x4.shared.b16 {%0,%1,%2,%3}, [%4];"
                 : "=r"(r0), "=r"(r1), "=r"(r2), "=r"(r3) : "r"(addr));
}
static __device__ __forceinline__ void ldm_x4_trans(uint32_t& r0, uint32_t& r1,
                                                    uint32_t& r2, uint32_t& r3, uint32_t addr) {
    asm volatile("ldmatrix.sync.aligned.m8n8.x4.trans.shared.b16 {%0,%1,%2,%3}, [%4];"
                 : "=r"(r0), "=r"(r1), "=r"(r2), "=r"(r3) : "r"(addr));
}
static __device__ __forceinline__ void mma16816(float& c0, float& c1, float& c2, float& c3,
                                                uint32_t a0, uint32_t a1, uint32_t a2, uint32_t a3,
                                                uint32_t b0, uint32_t b1) {
    asm volatile(
        "mma.sync.aligned.m16n8k16.row.col.f32.f16.f16.f32 "
        "{%0,%1,%2,%3}, {%4,%5,%6,%7}, {%8,%9}, {%0,%1,%2,%3};"
        : "+f"(c0), "+f"(c1), "+f"(c2), "+f"(c3)
        : "r"(a0), "r"(a1), "r"(a2), "r"(a3), "r"(b0), "r"(b1));
}

extern __shared__ char smem[];

__global__ void __launch_bounds__(256, 2)
pce_gemm_kernel(float* __restrict__ out)
{
    const int tid  = threadIdx.x;
    const int wid  = tid >> 5;
    const int lane = tid & 31;
    // reversed tile order: start on the psi tiles most recently written (L2-hot)
    const int m0   = (int)(gridDim.x - 1 - blockIdx.x) * MTILE;

    const uint32_t sbase = smem_u32(smem);

    auto load_stage = [&](int c, int buf) {
        // A: 64 k-rows x 128B from psi16[k][m0..m0+64); 512 granules / 256 thr
        const uint32_t adst = sbase + OFF_A + buf * ABUF_BYTES;
        #pragma unroll
        for (int j = 0; j < 2; j++) {
            int idx = tid + j * 256;             // 0..511
            int row = idx >> 3, g = idx & 7;
            cp_async16(adst + row * AROWB + g * 16,
                       psi16 + (size_t)(c * KC + row) * NSAMP + m0 + g * 8);
        }
        // B: 256 n-rows x 128B from w16g; 2048 granules / 256 thr
        const uint32_t bdst = sbase + OFF_B + buf * BBUF_BYTES;
        #pragma unroll
        for (int j = 0; j < 8; j++) {
            int idx = tid + j * 256;             // 0..2047
            int n = idx >> 3, g = idx & 7;
            cp_async16(bdst + n * BROWB + g * 16,
                       w16g + (size_t)n * KPAD + c * KC + g * 8);
        }
        CP_COMMIT();
    };

    // warp tiling: 2(m) x 4(n), each 32m x 64n
    const int warp_m = wid >> 2;   // 0..1
    const int warp_n = wid & 3;    // 0..3

    float acc[2][8][4];
    #pragma unroll
    for (int a = 0; a < 2; a++)
        #pragma unroll
        for (int b = 0; b < 8; b++)
            #pragma unroll
            for (int r = 0; r < 4; r++) acc[a][b][r] = 0.f;

    load_stage(0, 0);

    const int a_row_off = (lane & 7) + ((lane >> 4) & 1) * 8;
    const int a_m_off   = ((lane >> 3) & 1) * 8;

    for (int c = 0; c < NCHUNK; c++) {
        const int cb = c & 1;
        CP_WAIT0();
        __syncthreads();

        if (c + 1 < NCHUNK)
            load_stage(c + 1, cb ^ 1);

        const uint32_t abase = sbase + OFF_A + cb * ABUF_BYTES;
        const uint32_t b_base = sbase + OFF_B + cb * BBUF_BYTES
                              + (warp_n * 64 + ((lane >> 4) * 8) + (lane & 7)) * BROWB
                              + ((lane >> 3) & 1) * 16;

        #pragma unroll
        for (int kb = 0; kb < 4; kb++) {
            uint32_t af[2][4], bf[4][4];
            #pragma unroll
            for (int mb = 0; mb < 2; mb++)
                ldm_x4_trans(af[mb][0], af[mb][1], af[mb][2], af[mb][3],
                             abase + (kb * 16 + a_row_off) * AROWB
                                   + (warp_m * 32 + mb * 16 + a_m_off) * 2);
            #pragma unroll
            for (int np = 0; np < 4; np++)
                ldm_x4(bf[np][0], bf[np][1], bf[np][2], bf[np][3],
                       b_base + np * 16 * BROWB + kb * 32);
            #pragma unroll
            for (int mb = 0; mb < 2; mb++)
                #pragma unroll
                for (int nb = 0; nb < 8; nb++)
                    mma16816(acc[mb][nb][0], acc[mb][nb][1], acc[mb][nb][2], acc[mb][nb][3],
                             af[mb][0], af[mb][1], af[mb][2], af[mb][3],
                             bf[nb >> 1][(nb & 1) * 2], bf[nb >> 1][(nb & 1) * 2 + 1]);
        }
    }

    // epilogue: direct fp32 stores
    {
        const int mw = m0 + warp_m * 32;
        const int nw = warp_n * 64;
        const int rq = lane >> 2;
        const int cq = 2 * (lane & 3);
        #pragma unroll
        for (int mb = 0; mb < 2; mb++) {
            #pragma unroll
            for (int nb = 0; nb < 8; nb++) {
                const int row = mw + mb * 16 + rq;
                const int col = nw + nb * 8 + cq;
                *(float2*)(out + (size_t)row * NOUT + col)
                    = make_float2(acc[mb][nb][0], acc[mb][nb][1]);
                *(float2*)(out + (size_t)(row + 8) * NOUT + col)
                    = make_float2(acc[mb][nb][2], acc[mb][nb][3]);
            }
        }
    }
}

extern "C" void kernel_launch(void* const* d_in, const int* in_sizes, int n_in,
                              void* d_out, int out_size) {
    const float* x   = (const float*)d_in[0];
    const float* wgt = (const float*)d_in[1];
    const int*   mi  = (const int*)d_in[2];
    float* out = (float*)d_out;

    pce_pre_kernel<<<512 + (NSAMP / PTILE) * KSPLIT, 256>>>(x, wgt, mi);

    cudaFuncSetAttribute(pce_gemm_kernel,
                         cudaFuncAttributeMaxDynamicSharedMemorySize, GEMM_SMEM);
    pce_gemm_kernel<<<NSAMP / MTILE, 256, GEMM_SMEM>>>(out);
}

// round 17
// speedup vs baseline: 1.6165x; 1.2211x over previous
#include <cuda_runtime.h>
#include <cuda_fp16.h>
#include <cstdint>

// ---------------- problem constants ----------------
#define NSAMP   131072
#define INF     8
#define NPCE    495
#define KPAD    512
#define NOUT    256
#define PTILE   128          // psi tile rows
#define MTILE   64           // GEMM CTA rows (R13-validated)
#define KC      64           // K per chunk
#define NCHUNK  (KPAD / KC)  // 8
#define NSTAGE  2

// A k-major [64 k][64 m] halves, row stride 144B (9x16B granules)
#define AROWB   144
#define ABUF_BYTES (KC * AROWB)          // 9216
// B n-major [256 n][64 k] halves, row stride 144B
#define BROWB   144
#define BBUF_BYTES (NOUT * BROWB)        // 36864
#define OFF_A   0
#define OFF_B   (NSTAGE * ABUF_BYTES)    // 18432
#define GEMM_SMEM (OFF_B + NSTAGE * BBUF_BYTES)   // 92160 (x2 CTAs = 184K)

// fp16 weights, zero-padded K, [NOUT][KPAD]
__device__ __half w16g[NOUT * KPAD];
// psi staged fp16, [k][m] layout (k-major rows of 131072 halves)
__device__ __align__(16) __half psi16[(size_t)KPAD * NSAMP];

static __device__ __forceinline__ uint32_t smem_u32(const void* p) {
    uint32_t a;
    asm("{ .reg .u64 t; cvta.to.shared.u64 t, %1; cvt.u32.u64 %0, t; }" : "=r"(a) : "l"(p));
    return a;
}

// ===== fused pre-kernel: blocks 0-511 convert W; blocks 512+ psi (half2 HT) ==
__global__ void __launch_bounds__(256)
pce_pre_kernel(const float* __restrict__ x, const float* __restrict__ wgt,
               const int* __restrict__ mi)
{
    const int tid = threadIdx.x;

    if (blockIdx.x < 512) {
        int idx = blockIdx.x * 256 + tid;        // 0..131071
        int n = idx >> 9, k = idx & (KPAD - 1);
        w16g[idx] = __float2half(k < NPCE ? wgt[n * NPCE + k] : 0.0f);
        return;
    }

    // ---- psi generation: one block per 128-sample tile, HT in half2 ----
    __shared__ unsigned mi_s[KPAD];
    __shared__ __half2  ht2[40 * 64];       // HT[off][mp], mp = sample pair
    const int m0 = (blockIdx.x - 512) * PTILE;

    for (int t = tid; t < KPAD; t += 256) {
        unsigned packed = 0;
        if (t < NPCE) {
            int slot = 0;
            #pragma unroll
            for (int j = 0; j < INF; j++) {
                int o = mi[t * INF + j];
                if (o > 0) { packed |= (unsigned)(j * 5 + o) << (8 * slot); slot++; }
            }
        }
        mi_s[t] = packed;
    }

    // build: thread tid<64 handles sample pair (2*tid, 2*tid+1)
    if (tid < 64) {
        const float4* xra = (const float4*)(x + (size_t)(m0 + 2 * tid) * INF);
        const float4* xrb = (const float4*)(x + (size_t)(m0 + 2 * tid + 1) * INF);
        float4 a0 = xra[0], a1 = xra[1], b0 = xrb[0], b1 = xrb[1];
        float va[8] = {a0.x, a0.y, a0.z, a0.w, a1.x, a1.y, a1.z, a1.w};
        float vb[8] = {b0.x, b0.y, b0.z, b0.w, b1.x, b1.y, b1.z, b1.w};
        #pragma unroll
        for (int j = 0; j < INF; j++) {
            float pa = va[j], pb = vb[j];
            float a2 = pa * pa - 1.f,      b2 = pb * pb - 1.f;
            float a3 = pa * a2 - 2.f * pa, b3 = pb * b2 - 2.f * pb;
            float a4 = pa * a3 - 3.f * a2, b4 = pb * b3 - 3.f * b2;
            ht2[(j * 5 + 0) * 64 + tid] = __floats2half2_rn(1.f, 1.f);
            ht2[(j * 5 + 1) * 64 + tid] = __floats2half2_rn(pa, pb);
            ht2[(j * 5 + 2) * 64 + tid] =
                __floats2half2_rn(a2 * 0.70710678118654752f, b2 * 0.70710678118654752f);
            ht2[(j * 5 + 3) * 64 + tid] =
                __floats2half2_rn(a3 * 0.40824829046386302f, b3 * 0.40824829046386302f);
            ht2[(j * 5 + 4) * 64 + tid] =
                __floats2half2_rn(a4 * 0.20412414523193151f, b4 * 0.20412414523193151f);
        }
    }
    __syncthreads();

    // main: 512 k-rows x 32 mp-slots (2 chains: mp and mp+32); 64 iters
    #pragma unroll 4
    for (int it = 0; it < 64; it++) {
        int idx = it * 256 + tid;             // 0..16383
        int k = idx >> 5, mp = idx & 31;
        unsigned p = mi_s[k];
        __half2 c0 = ht2[(p & 255) * 64 + mp];        // p==0 -> ones
        __half2 c1 = ht2[(p & 255) * 64 + mp + 32];
        p >>= 8;
        while (p) {                           // warp-uniform slot-count skip
            c0 = __hmul2(c0, ht2[(p & 255) * 64 + mp]);
            c1 = __hmul2(c1, ht2[(p & 255) * 64 + mp + 32]);
            p >>= 8;
        }
        __half* dst = psi16 + (size_t)k * NSAMP + m0 + 2 * mp;
        *(__half2*)dst        = c0;           // samples m0+2mp, +1
        *(__half2*)(dst + 64) = c1;           // samples m0+64+2mp, +1
    }
}

// ================= GEMM (byte-identical to R13) ==============================
static __device__ __forceinline__ void cp_async16(uint32_t dst, const void* src) {
    asm volatile("cp.async.cg.shared.global [%0], [%1], 16;" :: "r"(dst), "l"(src));
}
#define CP_COMMIT() asm volatile("cp.async.commit_group;" ::: "memory")
#define CP_WAIT0()  asm volatile("cp.async.wait_group 0;" ::: "memory")

static __device__ __forceinline__ void ldm_x4(uint32_t& r0, uint32_t& r1,
                                              uint32_t& r2, uint32_t& r3, uint32_t addr) {
    asm volatile("ldmatrix.sync.aligned.m8n8.x4.shared.b16 {%0,%1,%2,%3}, [%4];"
                 : "=r"(r0), "=r"(r1), "=r"(r2), "=r"(r3) : "r"(addr));
}
static __device__ __forceinline__ void ldm_x4_trans(uint32_t& r0, uint32_t& r1,
                                                    uint32_t& r2, uint32_t& r3, uint32_t addr) {
    asm volatile("ldmatrix.sync.aligned.m8n8.x4.trans.shared.b16 {%0,%1,%2,%3}, [%4];"
                 : "=r"(r0), "=r"(r1), "=r"(r2), "=r"(r3) : "r"(addr));
}
static __device__ __forceinline__ void mma16816(float& c0, float& c1, float& c2, float& c3,
                                                uint32_t a0, uint32_t a1, uint32_t a2, uint32_t a3,
                                                uint32_t b0, uint32_t b1) {
    asm volatile(
        "mma.sync.aligned.m16n8k16.row.col.f32.f16.f16.f32 "
        "{%0,%1,%2,%3}, {%4,%5,%6,%7}, {%8,%9}, {%0,%1,%2,%3};"
        : "+f"(c0), "+f"(c1), "+f"(c2), "+f"(c3)
        : "r"(a0), "r"(a1), "r"(a2), "r"(a3), "r"(b0), "r"(b1));
}

extern __shared__ char smem[];

__global__ void __launch_bounds__(256, 2)
pce_gemm_kernel(float* __restrict__ out)
{
    const int tid  = threadIdx.x;
    const int wid  = tid >> 5;
    const int lane = tid & 31;
    // reversed tile order: start on the psi tiles most recently written (L2-hot)
    const int m0   = (int)(gridDim.x - 1 - blockIdx.x) * MTILE;

    const uint32_t sbase = smem_u32(smem);

    auto load_stage = [&](int c, int buf) {
        // A: 64 k-rows x 128B from psi16[k][m0..m0+64); 512 granules / 256 thr
        const uint32_t adst = sbase + OFF_A + buf * ABUF_BYTES;
        #pragma unroll
        for (int j = 0; j < 2; j++) {
            int idx = tid + j * 256;             // 0..511
            int row = idx >> 3, g = idx & 7;
            cp_async16(adst + row * AROWB + g * 16,
                       psi16 + (size_t)(c * KC + row) * NSAMP + m0 + g * 8);
        }
        // B: 256 n-rows x 128B from w16g; 2048 granules / 256 thr
        const uint32_t bdst = sbase + OFF_B + buf * BBUF_BYTES;
        #pragma unroll
        for (int j = 0; j < 8; j++) {
            int idx = tid + j * 256;             // 0..2047
            int n = idx >> 3, g = idx & 7;
            cp_async16(bdst + n * BROWB + g * 16,
                       w16g + (size_t)n * KPAD + c * KC + g * 8);
        }
        CP_COMMIT();
    };

    // warp tiling: 2(m) x 4(n), each 32m x 64n
    const int warp_m = wid >> 2;   // 0..1
    const int warp_n = wid & 3;    // 0..3

    float acc[2][8][4];
    #pragma unroll
    for (int a = 0; a < 2; a++)
        #pragma unroll
        for (int b = 0; b < 8; b++)
            #pragma unroll
            for (int r = 0; r < 4; r++) acc[a][b][r] = 0.f;

    load_stage(0, 0);

    const int a_row_off = (lane & 7) + ((lane >> 4) & 1) * 8;
    const int a_m_off   = ((lane >> 3) & 1) * 8;

    for (int c = 0; c < NCHUNK; c++) {
        const int cb = c & 1;
        CP_WAIT0();
        __syncthreads();

        if (c + 1 < NCHUNK)
            load_stage(c + 1, cb ^ 1);

        const uint32_t abase = sbase + OFF_A + cb * ABUF_BYTES;
        const uint32_t b_base = sbase + OFF_B + cb * BBUF_BYTES
                              + (warp_n * 64 + ((lane >> 4) * 8) + (lane & 7)) * BROWB
                              + ((lane >> 3) & 1) * 16;

        #pragma unroll
        for (int kb = 0; kb < 4; kb++) {
            uint32_t af[2][4], bf[4][4];
            #pragma unroll
            for (int mb = 0; mb < 2; mb++)
                ldm_x4_trans(af[mb][0], af[mb][1], af[mb][2], af[mb][3],
                             abase + (kb * 16 + a_row_off) * AROWB
                                   + (warp_m * 32 + mb * 16 + a_m_off) * 2);
            #pragma unroll
            for (int np = 0; np < 4; np++)
                ldm_x4(bf[np][0], bf[np][1], bf[np][2], bf[np][3],
                       b_base + np * 16 * BROWB + kb * 32);
            #pragma unroll
            for (int mb = 0; mb < 2; mb++)
                #pragma unroll
                for (int nb = 0; nb < 8; nb++)
                    mma16816(acc[mb][nb][0], acc[mb][nb][1], acc[mb][nb][2], acc[mb][nb][3],
                             af[mb][0], af[mb][1], af[mb][2], af[mb][3],
                             bf[nb >> 1][(nb & 1) * 2], bf[nb >> 1][(nb & 1) * 2 + 1]);
        }
    }

    // epilogue: direct fp32 stores
    {
        const int mw = m0 + warp_m * 32;
        const int nw = warp_n * 64;
        const int rq = lane >> 2;
        const int cq = 2 * (lane & 3);
        #pragma unroll
        for (int mb = 0; mb < 2; mb++) {
            #pragma unroll
            for (int nb = 0; nb < 8; nb++) {
                const int row = mw + mb * 16 + rq;
                const int col = nw + nb * 8 + cq;
                *(float2*)(out + (size_t)row * NOUT + col)
                    = make_float2(acc[mb][nb][0], acc[mb][nb][1]);
                *(float2*)(out + (size_t)(row + 8) * NOUT + col)
                    = make_float2(acc[mb][nb][2], acc[mb][nb][3]);
            }
        }
    }
}

extern "C" void kernel_launch(void* const* d_in, const int* in_sizes, int n_in,
                              void* d_out, int out_size) {
    const float* x   = (const float*)d_in[0];
    const float* wgt = (const float*)d_in[1];
    const int*   mi  = (const int*)d_in[2];
    float* out = (float*)d_out;

    pce_pre_kernel<<<512 + NSAMP / PTILE, 256>>>(x, wgt, mi);

    cudaFuncSetAttribute(pce_gemm_kernel,
                         cudaFuncAttributeMaxDynamicSharedMemorySize, GEMM_SMEM);
    pce_gemm_kernel<<<NSAMP / MTILE, 256, GEMM_SMEM>>>(out);
}